// round 14
// baseline (speedup 1.0000x reference)
#include <cuda_runtime.h>
#include <cuda_fp16.h>
#include <cstdint>

// ---------------- problem dims ----------------
#define BATCH 4
#define SEQ   2048
#define EMB   1024
#define HEADS 16
#define HDIM  64
#define MROWS (BATCH*SEQ)   // 8192
#define NQKV  (3*EMB)       // 3072

// ---------------- scratch (no allocations allowed) ----------------
__device__ __align__(256) __half g_z16[MROWS * EMB];
__device__ __align__(256) __half g_w16[4 * EMB * EMB];     // [n][k] transposed
__device__ __align__(256) __half g_act[MROWS * NQKV];      // fused q|k|v (q pre-scaled)
__device__ __align__(256) __half g_ctx16[MROWS * EMB];

// ---------------- helpers ----------------
__device__ __forceinline__ uint32_t smem_u32(const void* p) {
    uint32_t a;
    asm("{ .reg .u64 t; cvta.to.shared.u64 t, %1; cvt.u32.u64 %0, t; }" : "=r"(a) : "l"(p));
    return a;
}
__device__ __forceinline__ uint32_t sw128(uint32_t off) {
    return off ^ ((off >> 3) & 0x70);
}
__device__ __forceinline__ void cpa16(uint32_t dst, const void* src) {
    asm volatile("cp.async.cg.shared.global [%0], [%1], 16;" :: "r"(dst), "l"(src));
}
#define CP_COMMIT() asm volatile("cp.async.commit_group;" ::: "memory")
template<int N> __device__ __forceinline__ void cp_wait() {
    asm volatile("cp.async.wait_group %0;" :: "n"(N) : "memory");
}

__device__ __forceinline__ void ldsm4(uint32_t* r, uint32_t a) {
    asm volatile("ldmatrix.sync.aligned.m8n8.x4.shared.b16 {%0,%1,%2,%3}, [%4];"
        : "=r"(r[0]), "=r"(r[1]), "=r"(r[2]), "=r"(r[3]) : "r"(a));
}
__device__ __forceinline__ void ldsm4t(uint32_t* r, uint32_t a) {
    asm volatile("ldmatrix.sync.aligned.m8n8.x4.trans.shared.b16 {%0,%1,%2,%3}, [%4];"
        : "=r"(r[0]), "=r"(r[1]), "=r"(r[2]), "=r"(r[3]) : "r"(a));
}
__device__ __forceinline__ void mma16816(float* c, const uint32_t* a, uint32_t b0, uint32_t b1) {
    asm volatile("mma.sync.aligned.m16n8k16.row.col.f32.f16.f16.f32 "
        "{%0,%1,%2,%3}, {%4,%5,%6,%7}, {%8,%9}, {%0,%1,%2,%3};"
        : "+f"(c[0]), "+f"(c[1]), "+f"(c[2]), "+f"(c[3])
        : "r"(a[0]), "r"(a[1]), "r"(a[2]), "r"(a[3]), "r"(b0), "r"(b1));
}
// pack (lo, hi) floats -> fp16x2 register, round-to-nearest
__device__ __forceinline__ uint32_t f16x2(float lo, float hi) {
    uint32_t r;
    asm("cvt.rn.f16x2.f32 %0, %1, %2;" : "=r"(r) : "f"(hi), "f"(lo));
    return r;
}
// packed fp16x2 exp2
__device__ __forceinline__ uint32_t h2exp2(uint32_t x) {
    uint32_t r;
    asm("ex2.approx.f16x2 %0, %1;" : "=r"(r) : "r"(x));
    return r;
}
#define ONES16X2 0x3C003C00u   // (1.0h, 1.0h)

// ---------------- DSMEM helpers (cluster rank exchange) ----------------
__device__ __forceinline__ uint32_t mapa_rank(uint32_t addr, uint32_t rank) {
    uint32_t r;
    asm("mapa.shared::cluster.u32 %0, %1, %2;" : "=r"(r) : "r"(addr), "r"(rank));
    return r;
}
__device__ __forceinline__ float2 ld_dsmem_f2(uint32_t a) {
    float2 v;
    asm volatile("ld.shared::cluster.v2.f32 {%0,%1}, [%2];" : "=f"(v.x), "=f"(v.y) : "r"(a));
    return v;
}
__device__ __forceinline__ float ld_dsmem_f(uint32_t a) {
    float v;
    asm volatile("ld.shared::cluster.f32 %0, [%1];" : "=f"(v) : "r"(a));
    return v;
}
#define CLUSTER_ARRIVE() asm volatile("barrier.cluster.arrive.aligned;" ::: "memory")
#define CLUSTER_WAIT()   asm volatile("barrier.cluster.wait.aligned;" ::: "memory")

// ---------------- fused prep: weight transpose/convert + z convert ----------------
__global__ void prep_all(const float* __restrict__ w0, const float* __restrict__ w1,
                         const float* __restrict__ w2, const float* __restrict__ w3,
                         __half* __restrict__ wdst,
                         const float* __restrict__ z, __half* __restrict__ zh)
{
    if (blockIdx.z == 4) {
        int blk = blockIdx.y * 32 + blockIdx.x;          // 0..1023
        int tid = threadIdx.y * 32 + threadIdx.x;        // 0..255
        size_t base = (size_t)blk * 8192;
#pragma unroll
        for (int chunk = 0; chunk < 4; chunk++) {
            size_t i = base + chunk * 2048 + (size_t)tid * 8;
            float4 v0 = *(const float4*)(z + i);
            float4 v1 = *(const float4*)(z + i + 4);
            uint4 o;
            o.x = f16x2(v0.x, v0.y);
            o.y = f16x2(v0.z, v0.w);
            o.z = f16x2(v1.x, v1.y);
            o.w = f16x2(v1.z, v1.w);
            *(uint4*)&zh[i] = o;
        }
        return;
    }

    const float* srcs[4] = {w0, w1, w2, w3};
    const float* src = srcs[blockIdx.z];
    __half* d = wdst + (size_t)blockIdx.z * EMB * EMB;

    __shared__ float t[32][33];
    int x = blockIdx.x * 32 + threadIdx.x;
    int y0 = blockIdx.y * 32;
#pragma unroll
    for (int i = 0; i < 32; i += 8)
        t[threadIdx.y + i][threadIdx.x] = src[(size_t)(y0 + threadIdx.y + i) * EMB + x];
    __syncthreads();
    int on = blockIdx.x * 32 + threadIdx.y;
    int ok = y0 + threadIdx.x;
#pragma unroll
    for (int i = 0; i < 32; i += 8)
        d[(size_t)(on + i) * EMB + ok] = __float2half_rn(t[threadIdx.x][threadIdx.y + i]);
}

#define QSCALE  0.18033688011112042f   // 0.125 * log2(e)

// ---------------- QKV GEMM: CTA 64x128, 3 CTAs/SM ----------------
// Single-barrier pipeline: wait(t) -> sync -> issue(t+2) -> compute(t).
#define GQ_STAGE 24576
#define GQ_SMEM  (3 * GQ_STAGE)   // 73728

__global__ __launch_bounds__(128, 3) void gemm_qkv(
    const __half* __restrict__ A, const __half* __restrict__ B,
    __half* __restrict__ Ch, int M, int N, int K)
{
    extern __shared__ char smem[];
    const uint32_t sb = smem_u32(smem);
    const int tid = threadIdx.x;
    const int lane = tid & 31;
    const int wid = tid >> 5;
    const int wm = wid >> 1;
    const int wn = wid & 1;
    const int row0 = blockIdx.y * 64;
    const int col0 = blockIdx.x * 128;

    float c[2][8][4];
#pragma unroll
    for (int i = 0; i < 2; i++)
#pragma unroll
        for (int j = 0; j < 8; j++)
#pragma unroll
            for (int q = 0; q < 4; q++) c[i][j][q] = 0.f;

    const int aR = lane & 15;
    const int aC = (lane >> 4) * 16;
    const int bR = (lane & 7) + ((lane >> 4) & 1) * 8;
    const int bC = ((lane >> 3) & 1) * 16;

    auto load_chunk = [&](int kc, int st) {
        uint32_t base = sb + st * GQ_STAGE;
#pragma unroll
        for (int u = tid; u < 1536; u += 128) {
            if (u < 512) {       // A: 64 x 64
                int r = u >> 3, cu = u & 7;
                uint32_t off = sw128((uint32_t)(r * 128 + cu * 16));
                cpa16(base + off, A + (size_t)(row0 + r) * K + kc * 64 + cu * 8);
            } else {             // B: 128 x 64
                int v = u - 512;
                int r = v >> 3, cu = v & 7;
                uint32_t off = 8192 + sw128((uint32_t)(r * 128 + cu * 16));
                cpa16(base + off, B + (size_t)(col0 + r) * K + kc * 64 + cu * 8);
            }
        }
    };

    const int NCH = K / 64;
    load_chunk(0, 0); CP_COMMIT();
    load_chunk(1, 1); CP_COMMIT();

    for (int kc = 0; kc < NCH; kc++) {
        cp_wait<1>();
        __syncthreads();
        if (kc + 2 < NCH) { load_chunk(kc + 2, (kc + 2) % 3); CP_COMMIT(); }

        const uint32_t stb = sb + (kc % 3) * GQ_STAGE;
        const uint32_t AT = stb, BT = stb + 8192;
#pragma unroll
        for (int ks = 0; ks < 4; ks++) {
            uint32_t ah[2][4], bh[4][4];
#pragma unroll
            for (int am = 0; am < 2; am++)
                ldsm4(ah[am], AT + sw128((uint32_t)((wm*32 + am*16 + aR)*128 + aC + ks*32)));
#pragma unroll
            for (int bg = 0; bg < 4; bg++)
                ldsm4(bh[bg], BT + sw128((uint32_t)((wn*64 + bg*16 + bR)*128 + bC + ks*32)));
#pragma unroll
            for (int am = 0; am < 2; am++)
#pragma unroll
                for (int bn = 0; bn < 8; bn++)
                    mma16816(c[am][bn], ah[am], bh[bn>>1][(bn&1)*2], bh[bn>>1][(bn&1)*2+1]);
        }
    }

    const int g = lane >> 2;
    const int tg = lane & 3;
#pragma unroll
    for (int am = 0; am < 2; am++) {
#pragma unroll
        for (int bn = 0; bn < 8; bn++) {
            int r = row0 + wm * 32 + am * 16 + g;
            int cc = col0 + wn * 64 + bn * 8 + tg * 2;
            float sc = (cc < EMB) ? QSCALE : 1.0f;
            *(uint32_t*)&Ch[(size_t)r * N + cc] =
                f16x2(c[am][bn][0] * sc, c[am][bn][1] * sc);
            *(uint32_t*)&Ch[(size_t)(r + 8) * N + cc] =
                f16x2(c[am][bn][2] * sc, c[am][bn][3] * sc);
        }
    }
}

// ---------------- O-proj GEMM: CTA 128x128, 256 threads ----------------
// Single-barrier pipeline: wait(t) -> sync -> issue(t+2) -> compute(t).
#define G_STAGE 32768
#define G_SMEM  (3 * G_STAGE)   // 98304

__global__ __launch_bounds__(256, 2) void gemm_out(
    const __half* __restrict__ A, const __half* __restrict__ B,
    const float* __restrict__ bias, float* __restrict__ Cf, int M, int N, int K)
{
    extern __shared__ char smem[];
    const uint32_t sb = smem_u32(smem);
    const int tid = threadIdx.x;
    const int lane = tid & 31;
    const int wid = tid >> 5;
    const int wm = wid >> 2;      // 0..1
    const int wn = wid & 3;       // 0..3
    const int row0 = blockIdx.y * 128;
    const int col0 = blockIdx.x * 128;

    float c[4][4][4];
#pragma unroll
    for (int i = 0; i < 4; i++)
#pragma unroll
        for (int j = 0; j < 4; j++)
#pragma unroll
            for (int q = 0; q < 4; q++) c[i][j][q] = 0.f;

    const int aR = lane & 15;
    const int aC = (lane >> 4) * 16;
    const int bR = (lane & 7) + ((lane >> 4) & 1) * 8;
    const int bC = ((lane >> 3) & 1) * 16;

    auto load_chunk = [&](int kc, int st) {
        uint32_t base = sb + st * G_STAGE;
#pragma unroll
        for (int u = tid; u < 2048; u += 256) {
            int half = u >> 10;
            int r = (u >> 3) & 127;
            int cu = u & 7;
            uint32_t off = half * 16384 + sw128((uint32_t)(r * 128 + cu * 16));
            size_t g = half ? ((size_t)(col0 + r) * K + kc * 64 + cu * 8)
                            : ((size_t)(row0 + r) * K + kc * 64 + cu * 8);
            cpa16(base + off, (half ? B : A) + g);
        }
    };

    const int NCH = K / 64;
    load_chunk(0, 0); CP_COMMIT();
    load_chunk(1, 1); CP_COMMIT();

    for (int kc = 0; kc < NCH; kc++) {
        cp_wait<1>();
        __syncthreads();
        if (kc + 2 < NCH) { load_chunk(kc + 2, (kc + 2) % 3); CP_COMMIT(); }

        const uint32_t stb = sb + (kc % 3) * G_STAGE;
        const uint32_t AT = stb, BT = stb + 16384;
#pragma unroll
        for (int ks = 0; ks < 4; ks++) {
            uint32_t ah[4][4], bh[2][4];
#pragma unroll
            for (int am = 0; am < 4; am++)
                ldsm4(ah[am], AT + sw128((uint32_t)((wm*64 + am*16 + aR)*128 + aC + ks*32)));
#pragma unroll
            for (int bg = 0; bg < 2; bg++)
                ldsm4(bh[bg], BT + sw128((uint32_t)((wn*32 + bg*16 + bR)*128 + bC + ks*32)));
#pragma unroll
            for (int am = 0; am < 4; am++)
#pragma unroll
                for (int bn = 0; bn < 4; bn++)
                    mma16816(c[am][bn], ah[am], bh[bn>>1][(bn&1)*2], bh[bn>>1][(bn&1)*2+1]);
        }
    }

    const int g = lane >> 2;
    const int tg = lane & 3;
#pragma unroll
    for (int am = 0; am < 4; am++) {
#pragma unroll
        for (int bn = 0; bn < 4; bn++) {
            int r = row0 + wm * 64 + am * 16 + g;
            int cc = col0 + wn * 32 + bn * 8 + tg * 2;
            float2 v0 = make_float2(c[am][bn][0], c[am][bn][1]);
            float2 v1 = make_float2(c[am][bn][2], c[am][bn][3]);
            float b0 = bias[cc], b1 = bias[cc + 1];
            v0.x += b0; v0.y += b1; v1.x += b0; v1.y += b1;
            *(float2*)&Cf[(size_t)r * N + cc] = v0;
            *(float2*)&Cf[(size_t)(r + 8) * N + cc] = v1;
        }
    }
}

// ---------------- split-KV flash attention with cluster-pair DSMEM merge ----------------
// Single-barrier pipeline: wait(t) -> sync -> issue(t+2) -> compute(t).
#define KV_STAGE 16384
#define AT_SMEM  (16384 + 3 * KV_STAGE)   // 65536
#define EX_O     0u                       // 128 x 64 fp32 = 32 KB (dead Q + stage0)
#define EX_L     32768u                   // 128 fp32 row sums

__global__ __launch_bounds__(128, 3) void attn_pipe(
    const __half* __restrict__ act, __half* __restrict__ ctx)
{
    extern __shared__ char smem[];
    const uint32_t sb = smem_u32(smem);
    const uint32_t QT = sb;

    const int tid = threadIdx.x;
    const int lane = tid & 31;
    const int wid = tid >> 5;
    const int kvh = blockIdx.x;          // KV half == cluster rank
    const int q0 = blockIdx.y * 128;
    const int bh = blockIdx.z;
    const long rowBase = (long)(bh >> 4) * SEQ;
    const int h = bh & 15;
    const int hoff = h * HDIM;

    const int aR = lane & 15;
    const int aC = (lane >> 4) * 16;
    const int bR = (lane & 7) + ((lane >> 4) & 1) * 8;
    const int bC = ((lane >> 3) & 1) * 16;
    const int vR = (lane & 7) + ((lane >> 3) & 1) * 8;
    const int vC = (lane >> 4) * 16;

    // Q tile (pre-scaled by 0.125*log2e at QKV epilogue): 128 x 64 fp16
    for (int u = tid; u < 1024; u += 128) {
        int r = u >> 3, cu = u & 7;
        uint32_t off = sw128((uint32_t)(r * 128 + cu * 16));
        cpa16(QT + off, act + (size_t)(rowBase + q0 + r) * NQKV + hoff + cu * 8);
    }

    const int T = 16;                    // tiles in this half
    const int tbase = kvh * T;

    auto load_kv = [&](int t, int st) {
        uint32_t base = sb + 16384 + st * KV_STAGE;
        const int kv0 = (tbase + t) * 64;
#pragma unroll
        for (int u = tid; u < 1024; u += 128) {
            int half = u >> 9;           // 0 = K, 1 = V
            int r = (u >> 3) & 63;
            int cu = u & 7;
            uint32_t off = half * 8192 + sw128((uint32_t)(r * 128 + cu * 16));
            size_t g = (size_t)(rowBase + kv0 + r) * NQKV + EMB + half * EMB + hoff + cu * 8;
            cpa16(base + off, act + g);
        }
    };

    load_kv(0, 0); CP_COMMIT();          // group 0 includes Q
    load_kv(1, 1); CP_COMMIT();

    uint32_t aQ[2][4][4];
    float o[2][8][4];
#pragma unroll
    for (int mi = 0; mi < 2; mi++)
#pragma unroll
        for (int i = 0; i < 8; i++)
#pragma unroll
            for (int j = 0; j < 4; j++) o[mi][i][j] = 0.f;
    float la[2][4] = {{0.f,0.f,0.f,0.f},{0.f,0.f,0.f,0.f}};

    for (int t = 0; t < T; t++) {
        cp_wait<1>();
        __syncthreads();
        if (t + 2 < T) { load_kv(t + 2, (t + 2) % 3); CP_COMMIT(); }
        if (t == 0) {
#pragma unroll
            for (int mi = 0; mi < 2; mi++)
#pragma unroll
                for (int ks = 0; ks < 4; ks++)
                    ldsm4(aQ[mi][ks],
                          QT + sw128((uint32_t)((wid*32 + mi*16 + aR)*128 + aC + ks*32)));
        }

        const uint32_t stb = sb + 16384 + (t % 3) * KV_STAGE;
        const uint32_t KT = stb, VT = stb + 8192;

#pragma unroll
        for (int half = 0; half < 2; half++) {   // n32 kv columns per half
            float s[2][4][4];
#pragma unroll
            for (int mi = 0; mi < 2; mi++)
#pragma unroll
                for (int i = 0; i < 4; i++)
#pragma unroll
                    for (int j = 0; j < 4; j++) s[mi][i][j] = 0.f;

#pragma unroll
            for (int ks = 0; ks < 4; ks++) {
#pragma unroll
                for (int bg = 0; bg < 2; bg++) {
                    uint32_t bk[4];
                    ldsm4(bk, KT + sw128((uint32_t)((half*32 + bg*16 + bR)*128 + bC + ks*32)));
#pragma unroll
                    for (int mi = 0; mi < 2; mi++) {
                        mma16816(s[mi][bg*2],   aQ[mi][ks], bk[0], bk[1]);
                        mma16816(s[mi][bg*2+1], aQ[mi][ks], bk[2], bk[3]);
                    }
                }
            }

            uint32_t aP[2][2][4];
#pragma unroll
            for (int mi = 0; mi < 2; mi++)
#pragma unroll
                for (int kp = 0; kp < 2; kp++) {
                    aP[mi][kp][0] = h2exp2(f16x2(s[mi][2*kp][0],   s[mi][2*kp][1]));
                    aP[mi][kp][1] = h2exp2(f16x2(s[mi][2*kp][2],   s[mi][2*kp][3]));
                    aP[mi][kp][2] = h2exp2(f16x2(s[mi][2*kp+1][0], s[mi][2*kp+1][1]));
                    aP[mi][kp][3] = h2exp2(f16x2(s[mi][2*kp+1][2], s[mi][2*kp+1][3]));
                }

#pragma unroll
            for (int mi = 0; mi < 2; mi++)
#pragma unroll
                for (int kp = 0; kp < 2; kp++)
                    mma16816(la[mi], aP[mi][kp], ONES16X2, ONES16X2);

#pragma unroll
            for (int kp = 0; kp < 2; kp++) {
#pragma unroll
                for (int bg = 0; bg < 4; bg++) {
                    uint32_t bv[4];
                    ldsm4t(bv, VT + sw128((uint32_t)((half*32 + kp*16 + vR)*128 + bg*32 + vC)));
#pragma unroll
                    for (int mi = 0; mi < 2; mi++) {
                        mma16816(o[mi][bg*2],   aP[mi][kp], bv[0], bv[1]);
                        mma16816(o[mi][bg*2+1], aP[mi][kp], bv[2], bv[3]);
                    }
                }
            }
        }
    }
    __syncthreads();   // all warps done with smem before reuse as exchange buffer

    // ---- cluster-pair merge ----
    const int g = lane >> 2;
    const int tg = lane & 3;

    if (kvh == 1) {
#pragma unroll
        for (int mi = 0; mi < 2; mi++) {
            int rl = wid * 32 + mi * 16 + g;
#pragma unroll
            for (int bn = 0; bn < 8; bn++) {
                int cl = bn * 8 + tg * 2;
                *(float2*)(smem + EX_O + ((uint32_t)rl * 64 + cl) * 4) =
                    make_float2(o[mi][bn][0], o[mi][bn][1]);
                *(float2*)(smem + EX_O + ((uint32_t)(rl + 8) * 64 + cl) * 4) =
                    make_float2(o[mi][bn][2], o[mi][bn][3]);
            }
            if (tg == 0) {
                *(float*)(smem + EX_L + (uint32_t)rl * 4) = la[mi][0];
                *(float*)(smem + EX_L + (uint32_t)(rl + 8) * 4) = la[mi][2];
            }
        }
    }
    CLUSTER_ARRIVE();
    CLUSTER_WAIT();

    if (kvh == 0) {
        uint32_t peer = mapa_rank(sb, 1);
#pragma unroll
        for (int mi = 0; mi < 2; mi++) {
            int rl = wid * 32 + mi * 16 + g;
            float l0 = la[mi][0] + ld_dsmem_f(peer + EX_L + (uint32_t)rl * 4);
            float l1 = la[mi][2] + ld_dsmem_f(peer + EX_L + (uint32_t)(rl + 8) * 4);
            float inv0 = 1.f / l0, inv1 = 1.f / l1;
            long r = rowBase + q0 + rl;
#pragma unroll
            for (int bn = 0; bn < 8; bn++) {
                int cl = bn * 8 + tg * 2;
                float2 p0 = ld_dsmem_f2(peer + EX_O + ((uint32_t)rl * 64 + cl) * 4);
                float2 p1 = ld_dsmem_f2(peer + EX_O + ((uint32_t)(rl + 8) * 64 + cl) * 4);
                int cc = hoff + cl;
                *(uint32_t*)&ctx[(size_t)r * EMB + cc] =
                    f16x2((o[mi][bn][0] + p0.x) * inv0, (o[mi][bn][1] + p0.y) * inv0);
                *(uint32_t*)&ctx[(size_t)(r + 8) * EMB + cc] =
                    f16x2((o[mi][bn][2] + p1.x) * inv1, (o[mi][bn][3] + p1.y) * inv1);
            }
        }
    }
    // keep rank 1 resident until rank 0 finished reading its smem
    CLUSTER_ARRIVE();
    CLUSTER_WAIT();
}

// ---------------- launcher ----------------
extern "C" void kernel_launch(void* const* d_in, const int* in_sizes, int n_in,
                              void* d_out, int out_size)
{
    const float* z   = (const float*)d_in[0];
    const float* w_q = (const float*)d_in[1];
    const float* w_k = (const float*)d_in[2];
    const float* w_v = (const float*)d_in[3];
    const float* w_o = (const float*)d_in[4];
    const float* b_o = (const float*)d_in[5];
    float* out = (float*)d_out;

    __half *z16, *w16, *act, *ctx;
    cudaGetSymbolAddress((void**)&z16, g_z16);
    cudaGetSymbolAddress((void**)&w16, g_w16);
    cudaGetSymbolAddress((void**)&act, g_act);
    cudaGetSymbolAddress((void**)&ctx, g_ctx16);

    prep_all<<<dim3(32, 32, 5), dim3(32, 8)>>>(w_q, w_k, w_v, w_o, w16, z, z16);

    cudaFuncSetAttribute(gemm_qkv, cudaFuncAttributeMaxDynamicSharedMemorySize, GQ_SMEM);
    cudaFuncSetAttribute(gemm_out, cudaFuncAttributeMaxDynamicSharedMemorySize, G_SMEM);
    cudaFuncSetAttribute(attn_pipe, cudaFuncAttributeMaxDynamicSharedMemorySize, AT_SMEM);

    const size_t MM = (size_t)EMB * EMB;

    // fused QKV: CTA 64x128, N = 3072, fp16 out, q section scaled by 0.125*log2e
    dim3 qkvGrid(NQKV / 128, MROWS / 64);    // (24, 128) = 3072 CTAs
    gemm_qkv<<<qkvGrid, 128, GQ_SMEM>>>(z16, w16, act, MROWS, NQKV, EMB);

    // split-KV attention, cluster (2,1,1) pairs the two KV halves
    {
        cudaLaunchConfig_t cfg = {};
        cfg.gridDim = dim3(2, SEQ / 128, BATCH * HEADS);   // 2048 CTAs
        cfg.blockDim = dim3(128, 1, 1);
        cfg.dynamicSmemBytes = AT_SMEM;
        cudaLaunchAttribute attrs[1];
        attrs[0].id = cudaLaunchAttributeClusterDimension;
        attrs[0].val.clusterDim = {2, 1, 1};
        cfg.attrs = attrs;
        cfg.numAttrs = 1;
        cudaLaunchKernelEx(&cfg, attn_pipe, (const __half*)act, (__half*)ctx);
    }

    dim3 ogrid(EMB / 128, MROWS / 128);      // (8, 64)
    gemm_out<<<ogrid, 256, G_SMEM>>>(ctx, w16 + 3 * MM, b_o, out, MROWS, EMB, EMB);
}

// round 15
// speedup vs baseline: 1.0139x; 1.0139x over previous
#include <cuda_runtime.h>
#include <cuda_fp16.h>
#include <cstdint>

// ---------------- problem dims ----------------
#define BATCH 4
#define SEQ   2048
#define EMB   1024
#define HEADS 16
#define HDIM  64
#define MROWS (BATCH*SEQ)   // 8192
#define NQKV  (3*EMB)       // 3072

// ---------------- scratch (no allocations allowed) ----------------
__device__ __align__(256) __half g_z16[MROWS * EMB];
__device__ __align__(256) __half g_w16[4 * EMB * EMB];     // [n][k] transposed
__device__ __align__(256) __half g_act[MROWS * NQKV];      // fused q|k|v (q pre-scaled)
__device__ __align__(256) __half g_ctx16[MROWS * EMB];

// ---------------- helpers ----------------
__device__ __forceinline__ uint32_t smem_u32(const void* p) {
    uint32_t a;
    asm("{ .reg .u64 t; cvta.to.shared.u64 t, %1; cvt.u32.u64 %0, t; }" : "=r"(a) : "l"(p));
    return a;
}
__device__ __forceinline__ uint32_t sw128(uint32_t off) {
    return off ^ ((off >> 3) & 0x70);
}
__device__ __forceinline__ uint32_t sw64(uint32_t off) {
    return off ^ ((off >> 3) & 0x30);
}
__device__ __forceinline__ void cpa16(uint32_t dst, const void* src) {
    asm volatile("cp.async.cg.shared.global [%0], [%1], 16;" :: "r"(dst), "l"(src));
}
#define CP_COMMIT() asm volatile("cp.async.commit_group;" ::: "memory")
template<int N> __device__ __forceinline__ void cp_wait() {
    asm volatile("cp.async.wait_group %0;" :: "n"(N) : "memory");
}

__device__ __forceinline__ void ldsm4(uint32_t* r, uint32_t a) {
    asm volatile("ldmatrix.sync.aligned.m8n8.x4.shared.b16 {%0,%1,%2,%3}, [%4];"
        : "=r"(r[0]), "=r"(r[1]), "=r"(r[2]), "=r"(r[3]) : "r"(a));
}
__device__ __forceinline__ void ldsm4t(uint32_t* r, uint32_t a) {
    asm volatile("ldmatrix.sync.aligned.m8n8.x4.trans.shared.b16 {%0,%1,%2,%3}, [%4];"
        : "=r"(r[0]), "=r"(r[1]), "=r"(r[2]), "=r"(r[3]) : "r"(a));
}
__device__ __forceinline__ void mma16816(float* c, const uint32_t* a, uint32_t b0, uint32_t b1) {
    asm volatile("mma.sync.aligned.m16n8k16.row.col.f32.f16.f16.f32 "
        "{%0,%1,%2,%3}, {%4,%5,%6,%7}, {%8,%9}, {%0,%1,%2,%3};"
        : "+f"(c[0]), "+f"(c[1]), "+f"(c[2]), "+f"(c[3])
        : "r"(a[0]), "r"(a[1]), "r"(a[2]), "r"(a[3]), "r"(b0), "r"(b1));
}
// pack (lo, hi) floats -> fp16x2 register, round-to-nearest
__device__ __forceinline__ uint32_t f16x2(float lo, float hi) {
    uint32_t r;
    asm("cvt.rn.f16x2.f32 %0, %1, %2;" : "=r"(r) : "f"(hi), "f"(lo));
    return r;
}
// packed fp16x2 exp2
__device__ __forceinline__ uint32_t h2exp2(uint32_t x) {
    uint32_t r;
    asm("ex2.approx.f16x2 %0, %1;" : "=r"(r) : "r"(x));
    return r;
}
#define ONES16X2 0x3C003C00u   // (1.0h, 1.0h)

// ---------------- DSMEM helpers (cluster rank exchange) ----------------
__device__ __forceinline__ uint32_t mapa_rank(uint32_t addr, uint32_t rank) {
    uint32_t r;
    asm("mapa.shared::cluster.u32 %0, %1, %2;" : "=r"(r) : "r"(addr), "r"(rank));
    return r;
}
__device__ __forceinline__ float2 ld_dsmem_f2(uint32_t a) {
    float2 v;
    asm volatile("ld.shared::cluster.v2.f32 {%0,%1}, [%2];" : "=f"(v.x), "=f"(v.y) : "r"(a));
    return v;
}
__device__ __forceinline__ float ld_dsmem_f(uint32_t a) {
    float v;
    asm volatile("ld.shared::cluster.f32 %0, [%1];" : "=f"(v) : "r"(a));
    return v;
}
#define CLUSTER_ARRIVE() asm volatile("barrier.cluster.arrive.aligned;" ::: "memory")
#define CLUSTER_WAIT()   asm volatile("barrier.cluster.wait.aligned;" ::: "memory")

// ---------------- fused prep: weight transpose/convert + z convert ----------------
__global__ void prep_all(const float* __restrict__ w0, const float* __restrict__ w1,
                         const float* __restrict__ w2, const float* __restrict__ w3,
                         __half* __restrict__ wdst,
                         const float* __restrict__ z, __half* __restrict__ zh)
{
    if (blockIdx.z == 4) {
        int blk = blockIdx.y * 32 + blockIdx.x;          // 0..1023
        int tid = threadIdx.y * 32 + threadIdx.x;        // 0..255
        size_t base = (size_t)blk * 8192;
#pragma unroll
        for (int chunk = 0; chunk < 4; chunk++) {
            size_t i = base + chunk * 2048 + (size_t)tid * 8;
            float4 v0 = *(const float4*)(z + i);
            float4 v1 = *(const float4*)(z + i + 4);
            uint4 o;
            o.x = f16x2(v0.x, v0.y);
            o.y = f16x2(v0.z, v0.w);
            o.z = f16x2(v1.x, v1.y);
            o.w = f16x2(v1.z, v1.w);
            *(uint4*)&zh[i] = o;
        }
        return;
    }

    const float* srcs[4] = {w0, w1, w2, w3};
    const float* src = srcs[blockIdx.z];
    __half* d = wdst + (size_t)blockIdx.z * EMB * EMB;

    __shared__ float t[32][33];
    int x = blockIdx.x * 32 + threadIdx.x;
    int y0 = blockIdx.y * 32;
#pragma unroll
    for (int i = 0; i < 32; i += 8)
        t[threadIdx.y + i][threadIdx.x] = src[(size_t)(y0 + threadIdx.y + i) * EMB + x];
    __syncthreads();
    int on = blockIdx.x * 32 + threadIdx.y;
    int ok = y0 + threadIdx.x;
#pragma unroll
    for (int i = 0; i < 32; i += 8)
        d[(size_t)(on + i) * EMB + ok] = __float2half_rn(t[threadIdx.x][threadIdx.y + i]);
}

#define QSCALE  0.18033688011112042f   // 0.125 * log2(e)

// ---------------- QKV GEMM: CTA 64x128, 3 CTAs/SM (R12 proven config) ----------------
#define GQ_STAGE 24576
#define GQ_SMEM  (3 * GQ_STAGE)   // 73728

__global__ __launch_bounds__(128, 3) void gemm_qkv(
    const __half* __restrict__ A, const __half* __restrict__ B,
    __half* __restrict__ Ch, int M, int N, int K)
{
    extern __shared__ char smem[];
    const uint32_t sb = smem_u32(smem);
    const int tid = threadIdx.x;
    const int lane = tid & 31;
    const int wid = tid >> 5;
    const int wm = wid >> 1;
    const int wn = wid & 1;
    const int row0 = blockIdx.y * 64;
    const int col0 = blockIdx.x * 128;

    float c[2][8][4];
#pragma unroll
    for (int i = 0; i < 2; i++)
#pragma unroll
        for (int j = 0; j < 8; j++)
#pragma unroll
            for (int q = 0; q < 4; q++) c[i][j][q] = 0.f;

    const int aR = lane & 15;
    const int aC = (lane >> 4) * 16;
    const int bR = (lane & 7) + ((lane >> 4) & 1) * 8;
    const int bC = ((lane >> 3) & 1) * 16;

    auto load_chunk = [&](int kc, int st) {
        uint32_t base = sb + st * GQ_STAGE;
#pragma unroll
        for (int u = tid; u < 1536; u += 128) {
            if (u < 512) {       // A: 64 x 64
                int r = u >> 3, cu = u & 7;
                uint32_t off = sw128((uint32_t)(r * 128 + cu * 16));
                cpa16(base + off, A + (size_t)(row0 + r) * K + kc * 64 + cu * 8);
            } else {             // B: 128 x 64
                int v = u - 512;
                int r = v >> 3, cu = v & 7;
                uint32_t off = 8192 + sw128((uint32_t)(r * 128 + cu * 16));
                cpa16(base + off, B + (size_t)(col0 + r) * K + kc * 64 + cu * 8);
            }
        }
    };

    const int NCH = K / 64;
    load_chunk(0, 0); CP_COMMIT();
    load_chunk(1, 1); CP_COMMIT();
    load_chunk(2, 2); CP_COMMIT();

    for (int kc = 0; kc < NCH; kc++) {
        cp_wait<2>();
        __syncthreads();

        const uint32_t stb = sb + (kc % 3) * GQ_STAGE;
        const uint32_t AT = stb, BT = stb + 8192;
#pragma unroll
        for (int ks = 0; ks < 4; ks++) {
            uint32_t ah[2][4], bh[4][4];
#pragma unroll
            for (int am = 0; am < 2; am++)
                ldsm4(ah[am], AT + sw128((uint32_t)((wm*32 + am*16 + aR)*128 + aC + ks*32)));
#pragma unroll
            for (int bg = 0; bg < 4; bg++)
                ldsm4(bh[bg], BT + sw128((uint32_t)((wn*64 + bg*16 + bR)*128 + bC + ks*32)));
#pragma unroll
            for (int am = 0; am < 2; am++)
#pragma unroll
                for (int bn = 0; bn < 8; bn++)
                    mma16816(c[am][bn], ah[am], bh[bn>>1][(bn&1)*2], bh[bn>>1][(bn&1)*2+1]);
        }
        __syncthreads();
        if (kc + 3 < NCH) { load_chunk(kc + 3, kc % 3); CP_COMMIT(); }
    }

    const int g = lane >> 2;
    const int tg = lane & 3;
#pragma unroll
    for (int am = 0; am < 2; am++) {
#pragma unroll
        for (int bn = 0; bn < 8; bn++) {
            int r = row0 + wm * 32 + am * 16 + g;
            int cc = col0 + wn * 64 + bn * 8 + tg * 2;
            float sc = (cc < EMB) ? QSCALE : 1.0f;
            *(uint32_t*)&Ch[(size_t)r * N + cc] =
                f16x2(c[am][bn][0] * sc, c[am][bn][1] * sc);
            *(uint32_t*)&Ch[(size_t)(r + 8) * N + cc] =
                f16x2(c[am][bn][2] * sc, c[am][bn][3] * sc);
        }
    }
}

// ---------------- O-proj GEMM: CTA 128x128, 256 threads, 4-stage KC=32 ----------------
// wait(t) -> one sync -> issue(t+3 into dead buffer (t+3)%4) -> compute(t).
// 64-byte rows use SW64 swizzle (conflict-free for ldmatrix + cp.async).
#define GO_STAGE 16384                 // A 128x32 fp16 (8KB) + B 128x32 (8KB)
#define GO_SMEM  (4 * GO_STAGE)        // 65536

__global__ __launch_bounds__(256, 2) void gemm_out(
    const __half* __restrict__ A, const __half* __restrict__ B,
    const float* __restrict__ bias, float* __restrict__ Cf, int M, int N, int K)
{
    extern __shared__ char smem[];
    const uint32_t sb = smem_u32(smem);
    const int tid = threadIdx.x;
    const int lane = tid & 31;
    const int wid = tid >> 5;
    const int wm = wid >> 2;      // 0..1
    const int wn = wid & 3;       // 0..3
    const int row0 = blockIdx.y * 128;
    const int col0 = blockIdx.x * 128;

    float c[4][4][4];
#pragma unroll
    for (int i = 0; i < 4; i++)
#pragma unroll
        for (int j = 0; j < 4; j++)
#pragma unroll
            for (int q = 0; q < 4; q++) c[i][j][q] = 0.f;

    const int aR = lane & 15;
    const int aC = (lane >> 4) * 16;
    const int bR = (lane & 7) + ((lane >> 4) & 1) * 8;
    const int bC = ((lane >> 3) & 1) * 16;

    // one chunk = 128 rows A + 128 rows B, 32 k-cols (64 bytes/row, SW64)
    auto load_chunk = [&](int kc, int st) {
        uint32_t base = sb + st * GO_STAGE;
#pragma unroll
        for (int u = tid; u < 1024; u += 256) {
            int half = u >> 9;           // 0 = A, 1 = B
            int r = (u >> 2) & 127;
            int cu = u & 3;
            uint32_t off = half * 8192 + sw64((uint32_t)(r * 64 + cu * 16));
            size_t g = half ? ((size_t)(col0 + r) * K + kc * 32 + cu * 8)
                            : ((size_t)(row0 + r) * K + kc * 32 + cu * 8);
            cpa16(base + off, (half ? B : A) + g);
        }
    };

    const int NCH = K / 32;   // 32 chunks
    load_chunk(0, 0); CP_COMMIT();
    load_chunk(1, 1); CP_COMMIT();
    load_chunk(2, 2); CP_COMMIT();

    for (int kc = 0; kc < NCH; kc++) {
        cp_wait<2>();
        __syncthreads();
        if (kc + 3 < NCH) { load_chunk(kc + 3, (kc + 3) & 3); CP_COMMIT(); }

        const uint32_t stb = sb + (kc & 3) * GO_STAGE;
        const uint32_t AT = stb, BT = stb + 8192;
#pragma unroll
        for (int ks = 0; ks < 2; ks++) {
            uint32_t ah[4][4], bh[2][4];
#pragma unroll
            for (int am = 0; am < 4; am++)
                ldsm4(ah[am], AT + sw64((uint32_t)((wm*64 + am*16 + aR)*64 + aC + ks*32)));
#pragma unroll
            for (int bg = 0; bg < 2; bg++)
                ldsm4(bh[bg], BT + sw64((uint32_t)((wn*32 + bg*16 + bR)*64 + bC + ks*32)));
#pragma unroll
            for (int am = 0; am < 4; am++)
#pragma unroll
                for (int bn = 0; bn < 4; bn++)
                    mma16816(c[am][bn], ah[am], bh[bn>>1][(bn&1)*2], bh[bn>>1][(bn&1)*2+1]);
        }
    }

    const int g = lane >> 2;
    const int tg = lane & 3;
#pragma unroll
    for (int am = 0; am < 4; am++) {
#pragma unroll
        for (int bn = 0; bn < 4; bn++) {
            int r = row0 + wm * 64 + am * 16 + g;
            int cc = col0 + wn * 32 + bn * 8 + tg * 2;
            float2 v0 = make_float2(c[am][bn][0], c[am][bn][1]);
            float2 v1 = make_float2(c[am][bn][2], c[am][bn][3]);
            float b0 = bias[cc], b1 = bias[cc + 1];
            v0.x += b0; v0.y += b1; v1.x += b0; v1.y += b1;
            *(float2*)&Cf[(size_t)r * N + cc] = v0;
            *(float2*)&Cf[(size_t)(r + 8) * N + cc] = v1;
        }
    }
}

// ---------------- split-KV flash attention with cluster-pair DSMEM merge (R12) ----------------
#define KV_STAGE 16384
#define AT_SMEM  (16384 + 3 * KV_STAGE)   // 65536
#define EX_O     0u                       // 128 x 64 fp32 = 32 KB (dead Q + stage0)
#define EX_L     32768u                   // 128 fp32 row sums

__global__ __launch_bounds__(128, 3) void attn_pipe(
    const __half* __restrict__ act, __half* __restrict__ ctx)
{
    extern __shared__ char smem[];
    const uint32_t sb = smem_u32(smem);
    const uint32_t QT = sb;

    const int tid = threadIdx.x;
    const int lane = tid & 31;
    const int wid = tid >> 5;
    const int kvh = blockIdx.x;          // KV half == cluster rank
    const int q0 = blockIdx.y * 128;
    const int bh = blockIdx.z;
    const long rowBase = (long)(bh >> 4) * SEQ;
    const int h = bh & 15;
    const int hoff = h * HDIM;

    const int aR = lane & 15;
    const int aC = (lane >> 4) * 16;
    const int bR = (lane & 7) + ((lane >> 4) & 1) * 8;
    const int bC = ((lane >> 3) & 1) * 16;
    const int vR = (lane & 7) + ((lane >> 3) & 1) * 8;
    const int vC = (lane >> 4) * 16;

    // Q tile (pre-scaled by 0.125*log2e at QKV epilogue): 128 x 64 fp16
    for (int u = tid; u < 1024; u += 128) {
        int r = u >> 3, cu = u & 7;
        uint32_t off = sw128((uint32_t)(r * 128 + cu * 16));
        cpa16(QT + off, act + (size_t)(rowBase + q0 + r) * NQKV + hoff + cu * 8);
    }

    const int T = 16;                    // tiles in this half
    const int tbase = kvh * T;

    auto load_kv = [&](int t, int st) {
        uint32_t base = sb + 16384 + st * KV_STAGE;
        const int kv0 = (tbase + t) * 64;
#pragma unroll
        for (int u = tid; u < 1024; u += 128) {
            int half = u >> 9;           // 0 = K, 1 = V
            int r = (u >> 3) & 63;
            int cu = u & 7;
            uint32_t off = half * 8192 + sw128((uint32_t)(r * 128 + cu * 16));
            size_t g = (size_t)(rowBase + kv0 + r) * NQKV + EMB + half * EMB + hoff + cu * 8;
            cpa16(base + off, act + g);
        }
    };

    load_kv(0, 0); CP_COMMIT();          // group 0 includes Q
    load_kv(1, 1); CP_COMMIT();
    load_kv(2, 2); CP_COMMIT();

    cp_wait<2>();
    __syncthreads();
    uint32_t aQ[2][4][4];
#pragma unroll
    for (int mi = 0; mi < 2; mi++)
#pragma unroll
        for (int ks = 0; ks < 4; ks++)
            ldsm4(aQ[mi][ks],
                  QT + sw128((uint32_t)((wid*32 + mi*16 + aR)*128 + aC + ks*32)));

    float o[2][8][4];
#pragma unroll
    for (int mi = 0; mi < 2; mi++)
#pragma unroll
        for (int i = 0; i < 8; i++)
#pragma unroll
            for (int j = 0; j < 4; j++) o[mi][i][j] = 0.f;
    float la[2][4] = {{0.f,0.f,0.f,0.f},{0.f,0.f,0.f,0.f}};

    for (int t = 0; t < T; t++) {
        cp_wait<2>();
        __syncthreads();

        const uint32_t stb = sb + 16384 + (t % 3) * KV_STAGE;
        const uint32_t KT = stb, VT = stb + 8192;

#pragma unroll
        for (int half = 0; half < 2; half++) {   // n32 kv columns per half
            float s[2][4][4];
#pragma unroll
            for (int mi = 0; mi < 2; mi++)
#pragma unroll
                for (int i = 0; i < 4; i++)
#pragma unroll
                    for (int j = 0; j < 4; j++) s[mi][i][j] = 0.f;

#pragma unroll
            for (int ks = 0; ks < 4; ks++) {
#pragma unroll
                for (int bg = 0; bg < 2; bg++) {
                    uint32_t bk[4];
                    ldsm4(bk, KT + sw128((uint32_t)((half*32 + bg*16 + bR)*128 + bC + ks*32)));
#pragma unroll
                    for (int mi = 0; mi < 2; mi++) {
                        mma16816(s[mi][bg*2],   aQ[mi][ks], bk[0], bk[1]);
                        mma16816(s[mi][bg*2+1], aQ[mi][ks], bk[2], bk[3]);
                    }
                }
            }

            uint32_t aP[2][2][4];
#pragma unroll
            for (int mi = 0; mi < 2; mi++)
#pragma unroll
                for (int kp = 0; kp < 2; kp++) {
                    aP[mi][kp][0] = h2exp2(f16x2(s[mi][2*kp][0],   s[mi][2*kp][1]));
                    aP[mi][kp][1] = h2exp2(f16x2(s[mi][2*kp][2],   s[mi][2*kp][3]));
                    aP[mi][kp][2] = h2exp2(f16x2(s[mi][2*kp+1][0], s[mi][2*kp+1][1]));
                    aP[mi][kp][3] = h2exp2(f16x2(s[mi][2*kp+1][2], s[mi][2*kp+1][3]));
                }

#pragma unroll
            for (int mi = 0; mi < 2; mi++)
#pragma unroll
                for (int kp = 0; kp < 2; kp++)
                    mma16816(la[mi], aP[mi][kp], ONES16X2, ONES16X2);

#pragma unroll
            for (int kp = 0; kp < 2; kp++) {
#pragma unroll
                for (int bg = 0; bg < 4; bg++) {
                    uint32_t bv[4];
                    ldsm4t(bv, VT + sw128((uint32_t)((half*32 + kp*16 + vR)*128 + bg*32 + vC)));
#pragma unroll
                    for (int mi = 0; mi < 2; mi++) {
                        mma16816(o[mi][bg*2],   aP[mi][kp], bv[0], bv[1]);
                        mma16816(o[mi][bg*2+1], aP[mi][kp], bv[2], bv[3]);
                    }
                }
            }
        }

        __syncthreads();
        if (t + 3 < T) { load_kv(t + 3, t % 3); CP_COMMIT(); }
    }

    // ---- cluster-pair merge ----
    const int g = lane >> 2;
    const int tg = lane & 3;

    if (kvh == 1) {
#pragma unroll
        for (int mi = 0; mi < 2; mi++) {
            int rl = wid * 32 + mi * 16 + g;
#pragma unroll
            for (int bn = 0; bn < 8; bn++) {
                int cl = bn * 8 + tg * 2;
                *(float2*)(smem + EX_O + ((uint32_t)rl * 64 + cl) * 4) =
                    make_float2(o[mi][bn][0], o[mi][bn][1]);
                *(float2*)(smem + EX_O + ((uint32_t)(rl + 8) * 64 + cl) * 4) =
                    make_float2(o[mi][bn][2], o[mi][bn][3]);
            }
            if (tg == 0) {
                *(float*)(smem + EX_L + (uint32_t)rl * 4) = la[mi][0];
                *(float*)(smem + EX_L + (uint32_t)(rl + 8) * 4) = la[mi][2];
            }
        }
    }
    CLUSTER_ARRIVE();
    CLUSTER_WAIT();

    if (kvh == 0) {
        uint32_t peer = mapa_rank(sb, 1);
#pragma unroll
        for (int mi = 0; mi < 2; mi++) {
            int rl = wid * 32 + mi * 16 + g;
            float l0 = la[mi][0] + ld_dsmem_f(peer + EX_L + (uint32_t)rl * 4);
            float l1 = la[mi][2] + ld_dsmem_f(peer + EX_L + (uint32_t)(rl + 8) * 4);
            float inv0 = 1.f / l0, inv1 = 1.f / l1;
            long r = rowBase + q0 + rl;
#pragma unroll
            for (int bn = 0; bn < 8; bn++) {
                int cl = bn * 8 + tg * 2;
                float2 p0 = ld_dsmem_f2(peer + EX_O + ((uint32_t)rl * 64 + cl) * 4);
                float2 p1 = ld_dsmem_f2(peer + EX_O + ((uint32_t)(rl + 8) * 64 + cl) * 4);
                int cc = hoff + cl;
                *(uint32_t*)&ctx[(size_t)r * EMB + cc] =
                    f16x2((o[mi][bn][0] + p0.x) * inv0, (o[mi][bn][1] + p0.y) * inv0);
                *(uint32_t*)&ctx[(size_t)(r + 8) * EMB + cc] =
                    f16x2((o[mi][bn][2] + p1.x) * inv1, (o[mi][bn][3] + p1.y) * inv1);
            }
        }
    }
    // keep rank 1 resident until rank 0 finished reading its smem
    CLUSTER_ARRIVE();
    CLUSTER_WAIT();
}

// ---------------- launcher ----------------
extern "C" void kernel_launch(void* const* d_in, const int* in_sizes, int n_in,
                              void* d_out, int out_size)
{
    const float* z   = (const float*)d_in[0];
    const float* w_q = (const float*)d_in[1];
    const float* w_k = (const float*)d_in[2];
    const float* w_v = (const float*)d_in[3];
    const float* w_o = (const float*)d_in[4];
    const float* b_o = (const float*)d_in[5];
    float* out = (float*)d_out;

    __half *z16, *w16, *act, *ctx;
    cudaGetSymbolAddress((void**)&z16, g_z16);
    cudaGetSymbolAddress((void**)&w16, g_w16);
    cudaGetSymbolAddress((void**)&act, g_act);
    cudaGetSymbolAddress((void**)&ctx, g_ctx16);

    prep_all<<<dim3(32, 32, 5), dim3(32, 8)>>>(w_q, w_k, w_v, w_o, w16, z, z16);

    cudaFuncSetAttribute(gemm_qkv, cudaFuncAttributeMaxDynamicSharedMemorySize, GQ_SMEM);
    cudaFuncSetAttribute(gemm_out, cudaFuncAttributeMaxDynamicSharedMemorySize, GO_SMEM);
    cudaFuncSetAttribute(attn_pipe, cudaFuncAttributeMaxDynamicSharedMemorySize, AT_SMEM);

    const size_t MM = (size_t)EMB * EMB;

    // fused QKV: CTA 64x128, N = 3072, fp16 out, q section scaled by 0.125*log2e
    dim3 qkvGrid(NQKV / 128, MROWS / 64);    // (24, 128) = 3072 CTAs
    gemm_qkv<<<qkvGrid, 128, GQ_SMEM>>>(z16, w16, act, MROWS, NQKV, EMB);

    // split-KV attention, cluster (2,1,1) pairs the two KV halves
    {
        cudaLaunchConfig_t cfg = {};
        cfg.gridDim = dim3(2, SEQ / 128, BATCH * HEADS);   // 2048 CTAs
        cfg.blockDim = dim3(128, 1, 1);
        cfg.dynamicSmemBytes = AT_SMEM;
        cudaLaunchAttribute attrs[1];
        attrs[0].id = cudaLaunchAttributeClusterDimension;
        attrs[0].val.clusterDim = {2, 1, 1};
        cfg.attrs = attrs;
        cfg.numAttrs = 1;
        cudaLaunchKernelEx(&cfg, attn_pipe, (const __half*)act, (__half*)ctx);
    }

    dim3 ogrid(EMB / 128, MROWS / 128);      // (8, 64)
    gemm_out<<<ogrid, 256, GO_SMEM>>>(ctx, w16 + 3 * MM, b_o, out, MROWS, EMB, EMB);
}

// round 16
// speedup vs baseline: 1.0337x; 1.0196x over previous
#include <cuda_runtime.h>
#include <cuda_fp16.h>
#include <cstdint>

// ---------------- problem dims ----------------
#define BATCH 4
#define SEQ   2048
#define EMB   1024
#define HEADS 16
#define HDIM  64
#define MROWS (BATCH*SEQ)   // 8192
#define NQKV  (3*EMB)       // 3072

// ---------------- scratch (no allocations allowed) ----------------
__device__ __align__(256) __half g_z16[MROWS * EMB];
__device__ __align__(256) __half g_w16[4 * EMB * EMB];     // [n][k] transposed
__device__ __align__(256) __half g_act[MROWS * NQKV];      // fused q|k|v (q pre-scaled)
__device__ __align__(256) __half g_ctx16[MROWS * EMB];

// ---------------- helpers ----------------
__device__ __forceinline__ uint32_t smem_u32(const void* p) {
    uint32_t a;
    asm("{ .reg .u64 t; cvta.to.shared.u64 t, %1; cvt.u32.u64 %0, t; }" : "=r"(a) : "l"(p));
    return a;
}
__device__ __forceinline__ uint32_t sw128(uint32_t off) {
    return off ^ ((off >> 3) & 0x70);
}
__device__ __forceinline__ void cpa16(uint32_t dst, const void* src) {
    asm volatile("cp.async.cg.shared.global [%0], [%1], 16;" :: "r"(dst), "l"(src));
}
#define CP_COMMIT() asm volatile("cp.async.commit_group;" ::: "memory")
template<int N> __device__ __forceinline__ void cp_wait() {
    asm volatile("cp.async.wait_group %0;" :: "n"(N) : "memory");
}

__device__ __forceinline__ void ldsm4(uint32_t* r, uint32_t a) {
    asm volatile("ldmatrix.sync.aligned.m8n8.x4.shared.b16 {%0,%1,%2,%3}, [%4];"
        : "=r"(r[0]), "=r"(r[1]), "=r"(r[2]), "=r"(r[3]) : "r"(a));
}
__device__ __forceinline__ void ldsm4t(uint32_t* r, uint32_t a) {
    asm volatile("ldmatrix.sync.aligned.m8n8.x4.trans.shared.b16 {%0,%1,%2,%3}, [%4];"
        : "=r"(r[0]), "=r"(r[1]), "=r"(r[2]), "=r"(r[3]) : "r"(a));
}
__device__ __forceinline__ void mma16816(float* c, const uint32_t* a, uint32_t b0, uint32_t b1) {
    asm volatile("mma.sync.aligned.m16n8k16.row.col.f32.f16.f16.f32 "
        "{%0,%1,%2,%3}, {%4,%5,%6,%7}, {%8,%9}, {%0,%1,%2,%3};"
        : "+f"(c[0]), "+f"(c[1]), "+f"(c[2]), "+f"(c[3])
        : "r"(a[0]), "r"(a[1]), "r"(a[2]), "r"(a[3]), "r"(b0), "r"(b1));
}
// pack (lo, hi) floats -> fp16x2 register, round-to-nearest
__device__ __forceinline__ uint32_t f16x2(float lo, float hi) {
    uint32_t r;
    asm("cvt.rn.f16x2.f32 %0, %1, %2;" : "=r"(r) : "f"(hi), "f"(lo));
    return r;
}
// packed fp16x2 exp2
__device__ __forceinline__ uint32_t h2exp2(uint32_t x) {
    uint32_t r;
    asm("ex2.approx.f16x2 %0, %1;" : "=r"(r) : "r"(x));
    return r;
}
#define ONES16X2 0x3C003C00u   // (1.0h, 1.0h)

// ---------------- DSMEM helpers (cluster rank exchange) ----------------
__device__ __forceinline__ uint32_t mapa_rank(uint32_t addr, uint32_t rank) {
    uint32_t r;
    asm("mapa.shared::cluster.u32 %0, %1, %2;" : "=r"(r) : "r"(addr), "r"(rank));
    return r;
}
__device__ __forceinline__ float2 ld_dsmem_f2(uint32_t a) {
    float2 v;
    asm volatile("ld.shared::cluster.v2.f32 {%0,%1}, [%2];" : "=f"(v.x), "=f"(v.y) : "r"(a));
    return v;
}
__device__ __forceinline__ float ld_dsmem_f(uint32_t a) {
    float v;
    asm volatile("ld.shared::cluster.f32 %0, [%1];" : "=f"(v) : "r"(a));
    return v;
}
#define CLUSTER_ARRIVE() asm volatile("barrier.cluster.arrive.aligned;" ::: "memory")
#define CLUSTER_WAIT()   asm volatile("barrier.cluster.wait.aligned;" ::: "memory")

// ---------------- fused prep: weight transpose/convert + z convert ----------------
__global__ void prep_all(const float* __restrict__ w0, const float* __restrict__ w1,
                         const float* __restrict__ w2, const float* __restrict__ w3,
                         __half* __restrict__ wdst,
                         const float* __restrict__ z, __half* __restrict__ zh)
{
    if (blockIdx.z == 4) {
        int blk = blockIdx.y * 32 + blockIdx.x;          // 0..1023
        int tid = threadIdx.y * 32 + threadIdx.x;        // 0..255
        size_t base = (size_t)blk * 8192;
#pragma unroll
        for (int chunk = 0; chunk < 4; chunk++) {
            size_t i = base + chunk * 2048 + (size_t)tid * 8;
            float4 v0 = *(const float4*)(z + i);
            float4 v1 = *(const float4*)(z + i + 4);
            uint4 o;
            o.x = f16x2(v0.x, v0.y);
            o.y = f16x2(v0.z, v0.w);
            o.z = f16x2(v1.x, v1.y);
            o.w = f16x2(v1.z, v1.w);
            *(uint4*)&zh[i] = o;
        }
        return;
    }

    const float* srcs[4] = {w0, w1, w2, w3};
    const float* src = srcs[blockIdx.z];
    __half* d = wdst + (size_t)blockIdx.z * EMB * EMB;

    __shared__ float t[32][33];
    int x = blockIdx.x * 32 + threadIdx.x;
    int y0 = blockIdx.y * 32;
#pragma unroll
    for (int i = 0; i < 32; i += 8)
        t[threadIdx.y + i][threadIdx.x] = src[(size_t)(y0 + threadIdx.y + i) * EMB + x];
    __syncthreads();
    int on = blockIdx.x * 32 + threadIdx.y;
    int ok = y0 + threadIdx.x;
#pragma unroll
    for (int i = 0; i < 32; i += 8)
        d[(size_t)(on + i) * EMB + ok] = __float2half_rn(t[threadIdx.x][threadIdx.y + i]);
}

#define QSCALE  0.18033688011112042f   // 0.125 * log2(e)

// ---------------- QKV GEMM: CTA 64x128, 3 CTAs/SM (R12 proven config) ----------------
#define GQ_STAGE 24576
#define GQ_SMEM  (3 * GQ_STAGE)   // 73728

__global__ __launch_bounds__(128, 3) void gemm_qkv(
    const __half* __restrict__ A, const __half* __restrict__ B,
    __half* __restrict__ Ch, int M, int N, int K)
{
    extern __shared__ char smem[];
    const uint32_t sb = smem_u32(smem);
    const int tid = threadIdx.x;
    const int lane = tid & 31;
    const int wid = tid >> 5;
    const int wm = wid >> 1;
    const int wn = wid & 1;
    const int row0 = blockIdx.y * 64;
    const int col0 = blockIdx.x * 128;

    float c[2][8][4];
#pragma unroll
    for (int i = 0; i < 2; i++)
#pragma unroll
        for (int j = 0; j < 8; j++)
#pragma unroll
            for (int q = 0; q < 4; q++) c[i][j][q] = 0.f;

    const int aR = lane & 15;
    const int aC = (lane >> 4) * 16;
    const int bR = (lane & 7) + ((lane >> 4) & 1) * 8;
    const int bC = ((lane >> 3) & 1) * 16;

    auto load_chunk = [&](int kc, int st) {
        uint32_t base = sb + st * GQ_STAGE;
#pragma unroll
        for (int u = tid; u < 1536; u += 128) {
            if (u < 512) {       // A: 64 x 64
                int r = u >> 3, cu = u & 7;
                uint32_t off = sw128((uint32_t)(r * 128 + cu * 16));
                cpa16(base + off, A + (size_t)(row0 + r) * K + kc * 64 + cu * 8);
            } else {             // B: 128 x 64
                int v = u - 512;
                int r = v >> 3, cu = v & 7;
                uint32_t off = 8192 + sw128((uint32_t)(r * 128 + cu * 16));
                cpa16(base + off, B + (size_t)(col0 + r) * K + kc * 64 + cu * 8);
            }
        }
    };

    const int NCH = K / 64;
    load_chunk(0, 0); CP_COMMIT();
    load_chunk(1, 1); CP_COMMIT();
    load_chunk(2, 2); CP_COMMIT();

    for (int kc = 0; kc < NCH; kc++) {
        cp_wait<2>();
        __syncthreads();

        const uint32_t stb = sb + (kc % 3) * GQ_STAGE;
        const uint32_t AT = stb, BT = stb + 8192;
#pragma unroll
        for (int ks = 0; ks < 4; ks++) {
            uint32_t ah[2][4], bh[4][4];
#pragma unroll
            for (int am = 0; am < 2; am++)
                ldsm4(ah[am], AT + sw128((uint32_t)((wm*32 + am*16 + aR)*128 + aC + ks*32)));
#pragma unroll
            for (int bg = 0; bg < 4; bg++)
                ldsm4(bh[bg], BT + sw128((uint32_t)((wn*64 + bg*16 + bR)*128 + bC + ks*32)));
#pragma unroll
            for (int am = 0; am < 2; am++)
#pragma unroll
                for (int bn = 0; bn < 8; bn++)
                    mma16816(c[am][bn], ah[am], bh[bn>>1][(bn&1)*2], bh[bn>>1][(bn&1)*2+1]);
        }
        __syncthreads();
        if (kc + 3 < NCH) { load_chunk(kc + 3, kc % 3); CP_COMMIT(); }
    }

    const int g = lane >> 2;
    const int tg = lane & 3;
#pragma unroll
    for (int am = 0; am < 2; am++) {
#pragma unroll
        for (int bn = 0; bn < 8; bn++) {
            int r = row0 + wm * 32 + am * 16 + g;
            int cc = col0 + wn * 64 + bn * 8 + tg * 2;
            float sc = (cc < EMB) ? QSCALE : 1.0f;
            *(uint32_t*)&Ch[(size_t)r * N + cc] =
                f16x2(c[am][bn][0] * sc, c[am][bn][1] * sc);
            *(uint32_t*)&Ch[(size_t)(r + 8) * N + cc] =
                f16x2(c[am][bn][2] * sc, c[am][bn][3] * sc);
        }
    }
}

// ---------------- O-proj GEMM: CTA 128x128, 256 threads, KC=64, 3-stage (R12) ----------------
#define G_STAGE 32768
#define G_SMEM  (3 * G_STAGE)   // 98304

__global__ __launch_bounds__(256, 2) void gemm_out(
    const __half* __restrict__ A, const __half* __restrict__ B,
    const float* __restrict__ bias, float* __restrict__ Cf, int M, int N, int K)
{
    extern __shared__ char smem[];
    const uint32_t sb = smem_u32(smem);
    const int tid = threadIdx.x;
    const int lane = tid & 31;
    const int wid = tid >> 5;
    const int wm = wid >> 2;      // 0..1
    const int wn = wid & 3;       // 0..3
    const int row0 = blockIdx.y * 128;
    const int col0 = blockIdx.x * 128;

    float c[4][4][4];
#pragma unroll
    for (int i = 0; i < 4; i++)
#pragma unroll
        for (int j = 0; j < 4; j++)
#pragma unroll
            for (int q = 0; q < 4; q++) c[i][j][q] = 0.f;

    const int aR = lane & 15;
    const int aC = (lane >> 4) * 16;
    const int bR = (lane & 7) + ((lane >> 4) & 1) * 8;
    const int bC = ((lane >> 3) & 1) * 16;

    auto load_chunk = [&](int kc, int st) {
        uint32_t base = sb + st * G_STAGE;
#pragma unroll
        for (int u = tid; u < 2048; u += 256) {
            int half = u >> 10;
            int r = (u >> 3) & 127;
            int cu = u & 7;
            uint32_t off = half * 16384 + sw128((uint32_t)(r * 128 + cu * 16));
            size_t g = half ? ((size_t)(col0 + r) * K + kc * 64 + cu * 8)
                            : ((size_t)(row0 + r) * K + kc * 64 + cu * 8);
            cpa16(base + off, (half ? B : A) + g);
        }
    };

    const int NCH = K / 64;
    load_chunk(0, 0); CP_COMMIT();
    load_chunk(1, 1); CP_COMMIT();
    load_chunk(2, 2); CP_COMMIT();

    for (int kc = 0; kc < NCH; kc++) {
        cp_wait<2>();
        __syncthreads();

        const uint32_t stb = sb + (kc % 3) * G_STAGE;
        const uint32_t AT = stb, BT = stb + 16384;
#pragma unroll
        for (int ks = 0; ks < 4; ks++) {
            uint32_t ah[4][4], bh[2][4];
#pragma unroll
            for (int am = 0; am < 4; am++)
                ldsm4(ah[am], AT + sw128((uint32_t)((wm*64 + am*16 + aR)*128 + aC + ks*32)));
#pragma unroll
            for (int bg = 0; bg < 2; bg++)
                ldsm4(bh[bg], BT + sw128((uint32_t)((wn*32 + bg*16 + bR)*128 + bC + ks*32)));
#pragma unroll
            for (int am = 0; am < 4; am++)
#pragma unroll
                for (int bn = 0; bn < 4; bn++)
                    mma16816(c[am][bn], ah[am], bh[bn>>1][(bn&1)*2], bh[bn>>1][(bn&1)*2+1]);
        }
        __syncthreads();
        if (kc + 3 < NCH) { load_chunk(kc + 3, kc % 3); CP_COMMIT(); }
    }

    const int g = lane >> 2;
    const int tg = lane & 3;
#pragma unroll
    for (int am = 0; am < 4; am++) {
#pragma unroll
        for (int bn = 0; bn < 4; bn++) {
            int r = row0 + wm * 64 + am * 16 + g;
            int cc = col0 + wn * 32 + bn * 8 + tg * 2;
            float2 v0 = make_float2(c[am][bn][0], c[am][bn][1]);
            float2 v1 = make_float2(c[am][bn][2], c[am][bn][3]);
            float b0 = bias[cc], b1 = bias[cc + 1];
            v0.x += b0; v0.y += b1; v1.x += b0; v1.y += b1;
            *(float2*)&Cf[(size_t)r * N + cc] = v0;
            *(float2*)&Cf[(size_t)(r + 8) * N + cc] = v1;
        }
    }
}

// ---------------- split-KV flash attention, symmetric cluster-pair DSMEM merge ----------------
// Grid (2, SEQ/128, B*H), cluster (2,1,1). Rank r merges q rows [64r, 64r+64)
// (held by its warps 2r..2r+1) and publishes the other 64 rows to its smem for
// the peer. Both ranks merge and store ctx concurrently (halved serial tail
// vs the R12 asymmetric merge). fp32 add order identical to R12.
#define KV_STAGE 16384
#define AT_SMEM  (16384 + 3 * KV_STAGE)   // 65536
#define EX_O     0u                       // 64 x 64 fp32 = 16 KB published rows
#define EX_L     16384u                   // 64 fp32 row sums

__global__ __launch_bounds__(128, 3) void attn_pipe(
    const __half* __restrict__ act, __half* __restrict__ ctx)
{
    extern __shared__ char smem[];
    const uint32_t sb = smem_u32(smem);
    const uint32_t QT = sb;

    const int tid = threadIdx.x;
    const int lane = tid & 31;
    const int wid = tid >> 5;
    const int kvh = blockIdx.x;          // KV half == cluster rank
    const int q0 = blockIdx.y * 128;
    const int bh = blockIdx.z;
    const long rowBase = (long)(bh >> 4) * SEQ;
    const int h = bh & 15;
    const int hoff = h * HDIM;

    const int aR = lane & 15;
    const int aC = (lane >> 4) * 16;
    const int bR = (lane & 7) + ((lane >> 4) & 1) * 8;
    const int bC = ((lane >> 3) & 1) * 16;
    const int vR = (lane & 7) + ((lane >> 3) & 1) * 8;
    const int vC = (lane >> 4) * 16;

    // Q tile (pre-scaled by 0.125*log2e at QKV epilogue): 128 x 64 fp16
    for (int u = tid; u < 1024; u += 128) {
        int r = u >> 3, cu = u & 7;
        uint32_t off = sw128((uint32_t)(r * 128 + cu * 16));
        cpa16(QT + off, act + (size_t)(rowBase + q0 + r) * NQKV + hoff + cu * 8);
    }

    const int T = 16;                    // tiles in this half
    const int tbase = kvh * T;

    auto load_kv = [&](int t, int st) {
        uint32_t base = sb + 16384 + st * KV_STAGE;
        const int kv0 = (tbase + t) * 64;
#pragma unroll
        for (int u = tid; u < 1024; u += 128) {
            int half = u >> 9;           // 0 = K, 1 = V
            int r = (u >> 3) & 63;
            int cu = u & 7;
            uint32_t off = half * 8192 + sw128((uint32_t)(r * 128 + cu * 16));
            size_t g = (size_t)(rowBase + kv0 + r) * NQKV + EMB + half * EMB + hoff + cu * 8;
            cpa16(base + off, act + g);
        }
    };

    load_kv(0, 0); CP_COMMIT();          // group 0 includes Q
    load_kv(1, 1); CP_COMMIT();
    load_kv(2, 2); CP_COMMIT();

    cp_wait<2>();
    __syncthreads();
    uint32_t aQ[2][4][4];
#pragma unroll
    for (int mi = 0; mi < 2; mi++)
#pragma unroll
        for (int ks = 0; ks < 4; ks++)
            ldsm4(aQ[mi][ks],
                  QT + sw128((uint32_t)((wid*32 + mi*16 + aR)*128 + aC + ks*32)));

    float o[2][8][4];
#pragma unroll
    for (int mi = 0; mi < 2; mi++)
#pragma unroll
        for (int i = 0; i < 8; i++)
#pragma unroll
            for (int j = 0; j < 4; j++) o[mi][i][j] = 0.f;
    float la[2][4] = {{0.f,0.f,0.f,0.f},{0.f,0.f,0.f,0.f}};

    for (int t = 0; t < T; t++) {
        cp_wait<2>();
        __syncthreads();

        const uint32_t stb = sb + 16384 + (t % 3) * KV_STAGE;
        const uint32_t KT = stb, VT = stb + 8192;

#pragma unroll
        for (int half = 0; half < 2; half++) {   // n32 kv columns per half
            float s[2][4][4];
#pragma unroll
            for (int mi = 0; mi < 2; mi++)
#pragma unroll
                for (int i = 0; i < 4; i++)
#pragma unroll
                    for (int j = 0; j < 4; j++) s[mi][i][j] = 0.f;

#pragma unroll
            for (int ks = 0; ks < 4; ks++) {
#pragma unroll
                for (int bg = 0; bg < 2; bg++) {
                    uint32_t bk[4];
                    ldsm4(bk, KT + sw128((uint32_t)((half*32 + bg*16 + bR)*128 + bC + ks*32)));
#pragma unroll
                    for (int mi = 0; mi < 2; mi++) {
                        mma16816(s[mi][bg*2],   aQ[mi][ks], bk[0], bk[1]);
                        mma16816(s[mi][bg*2+1], aQ[mi][ks], bk[2], bk[3]);
                    }
                }
            }

            uint32_t aP[2][2][4];
#pragma unroll
            for (int mi = 0; mi < 2; mi++)
#pragma unroll
                for (int kp = 0; kp < 2; kp++) {
                    aP[mi][kp][0] = h2exp2(f16x2(s[mi][2*kp][0],   s[mi][2*kp][1]));
                    aP[mi][kp][1] = h2exp2(f16x2(s[mi][2*kp][2],   s[mi][2*kp][3]));
                    aP[mi][kp][2] = h2exp2(f16x2(s[mi][2*kp+1][0], s[mi][2*kp+1][1]));
                    aP[mi][kp][3] = h2exp2(f16x2(s[mi][2*kp+1][2], s[mi][2*kp+1][3]));
                }

#pragma unroll
            for (int mi = 0; mi < 2; mi++)
#pragma unroll
                for (int kp = 0; kp < 2; kp++)
                    mma16816(la[mi], aP[mi][kp], ONES16X2, ONES16X2);

#pragma unroll
            for (int kp = 0; kp < 2; kp++) {
#pragma unroll
                for (int bg = 0; bg < 4; bg++) {
                    uint32_t bv[4];
                    ldsm4t(bv, VT + sw128((uint32_t)((half*32 + kp*16 + vR)*128 + bg*32 + vC)));
#pragma unroll
                    for (int mi = 0; mi < 2; mi++) {
                        mma16816(o[mi][bg*2],   aP[mi][kp], bv[0], bv[1]);
                        mma16816(o[mi][bg*2+1], aP[mi][kp], bv[2], bv[3]);
                    }
                }
            }
        }

        __syncthreads();
        if (t + 3 < T) { load_kv(t + 3, t % 3); CP_COMMIT(); }
    }
    __syncthreads();   // mainloop smem dead before reuse as exchange buffer

    // ---- symmetric cluster-pair merge ----
    // warps 2*kvh..2*kvh+1 hold this rank's merge rows; the other two publish.
    const int g = lane >> 2;
    const int tg = lane & 3;
    const bool merger = ((wid >> 1) == kvh);

    if (!merger) {
        // publish local partials for rows this rank does NOT merge.
        // local row index within the published 64-row block:
        int prl = (wid & 1) * 32;   // 0 or 32 within publishing half
#pragma unroll
        for (int mi = 0; mi < 2; mi++) {
            int rl = prl + mi * 16 + g;
#pragma unroll
            for (int bn = 0; bn < 8; bn++) {
                int cl = bn * 8 + tg * 2;
                *(float2*)(smem + EX_O + ((uint32_t)rl * 64 + cl) * 4) =
                    make_float2(o[mi][bn][0], o[mi][bn][1]);
                *(float2*)(smem + EX_O + ((uint32_t)(rl + 8) * 64 + cl) * 4) =
                    make_float2(o[mi][bn][2], o[mi][bn][3]);
            }
            if (tg == 0) {
                *(float*)(smem + EX_L + (uint32_t)rl * 4) = la[mi][0];
                *(float*)(smem + EX_L + (uint32_t)(rl + 8) * 4) = la[mi][2];
            }
        }
    }
    CLUSTER_ARRIVE();
    CLUSTER_WAIT();

    if (merger) {
        uint32_t peer = mapa_rank(sb, 1 - kvh);
        int prl = (wid & 1) * 32;               // row index within peer's published block
#pragma unroll
        for (int mi = 0; mi < 2; mi++) {
            int rl = prl + mi * 16 + g;
            int grow = kvh * 64 + rl;           // global row within the 128-row Q tile
            float p_l0 = ld_dsmem_f(peer + EX_L + (uint32_t)rl * 4);
            float p_l1 = ld_dsmem_f(peer + EX_L + (uint32_t)(rl + 8) * 4);
            // preserve R12 add order: rank0 partial + rank1 partial
            float l0 = (kvh == 0) ? (la[mi][0] + p_l0) : (p_l0 + la[mi][0]);
            float l1 = (kvh == 0) ? (la[mi][2] + p_l1) : (p_l1 + la[mi][2]);
            float inv0 = 1.f / l0, inv1 = 1.f / l1;
            long r = rowBase + q0 + grow;
#pragma unroll
            for (int bn = 0; bn < 8; bn++) {
                int cl = bn * 8 + tg * 2;
                float2 p0 = ld_dsmem_f2(peer + EX_O + ((uint32_t)rl * 64 + cl) * 4);
                float2 p1 = ld_dsmem_f2(peer + EX_O + ((uint32_t)(rl + 8) * 64 + cl) * 4);
                float a0 = (kvh == 0) ? (o[mi][bn][0] + p0.x) : (p0.x + o[mi][bn][0]);
                float a1 = (kvh == 0) ? (o[mi][bn][1] + p0.y) : (p0.y + o[mi][bn][1]);
                float a2 = (kvh == 0) ? (o[mi][bn][2] + p1.x) : (p1.x + o[mi][bn][2]);
                float a3 = (kvh == 0) ? (o[mi][bn][3] + p1.y) : (p1.y + o[mi][bn][3]);
                int cc = hoff + cl;
                *(uint32_t*)&ctx[(size_t)r * EMB + cc] = f16x2(a0 * inv0, a1 * inv0);
                *(uint32_t*)&ctx[(size_t)(r + 8) * EMB + cc] = f16x2(a2 * inv1, a3 * inv1);
            }
        }
    }
    // keep both ranks resident until peers finished reading published smem
    CLUSTER_ARRIVE();
    CLUSTER_WAIT();
}

// ---------------- launcher ----------------
extern "C" void kernel_launch(void* const* d_in, const int* in_sizes, int n_in,
                              void* d_out, int out_size)
{
    const float* z   = (const float*)d_in[0];
    const float* w_q = (const float*)d_in[1];
    const float* w_k = (const float*)d_in[2];
    const float* w_v = (const float*)d_in[3];
    const float* w_o = (const float*)d_in[4];
    const float* b_o = (const float*)d_in[5];
    float* out = (float*)d_out;

    __half *z16, *w16, *act, *ctx;
    cudaGetSymbolAddress((void**)&z16, g_z16);
    cudaGetSymbolAddress((void**)&w16, g_w16);
    cudaGetSymbolAddress((void**)&act, g_act);
    cudaGetSymbolAddress((void**)&ctx, g_ctx16);

    prep_all<<<dim3(32, 32, 5), dim3(32, 8)>>>(w_q, w_k, w_v, w_o, w16, z, z16);

    cudaFuncSetAttribute(gemm_qkv, cudaFuncAttributeMaxDynamicSharedMemorySize, GQ_SMEM);
    cudaFuncSetAttribute(gemm_out, cudaFuncAttributeMaxDynamicSharedMemorySize, G_SMEM);
    cudaFuncSetAttribute(attn_pipe, cudaFuncAttributeMaxDynamicSharedMemorySize, AT_SMEM);

    const size_t MM = (size_t)EMB * EMB;

    // fused QKV: CTA 64x128, N = 3072, fp16 out, q section scaled by 0.125*log2e
    dim3 qkvGrid(NQKV / 128, MROWS / 64);    // (24, 128) = 3072 CTAs
    gemm_qkv<<<qkvGrid, 128, GQ_SMEM>>>(z16, w16, act, MROWS, NQKV, EMB);

    // split-KV attention, cluster (2,1,1) pairs the two KV halves
    {
        cudaLaunchConfig_t cfg = {};
        cfg.gridDim = dim3(2, SEQ / 128, BATCH * HEADS);   // 2048 CTAs
        cfg.blockDim = dim3(128, 1, 1);
        cfg.dynamicSmemBytes = AT_SMEM;
        cudaLaunchAttribute attrs[1];
        attrs[0].id = cudaLaunchAttributeClusterDimension;
        attrs[0].val.clusterDim = {2, 1, 1};
        cfg.attrs = attrs;
        cfg.numAttrs = 1;
        cudaLaunchKernelEx(&cfg, attn_pipe, (const __half*)act, (__half*)ctx);
    }

    dim3 ogrid(EMB / 128, MROWS / 128);      // (8, 64)
    gemm_out<<<ogrid, 256, G_SMEM>>>(ctx, w16 + 3 * MM, b_o, out, MROWS, EMB, EMB);
}